// round 1
// baseline (speedup 1.0000x reference)
#include <cuda_runtime.h>
#include <cuda_bf16.h>
#include <cstdint>

// Scratch: Y = X @ W   (100000 x 256 fp32)
#define MAX_NODES 100000
#define DIM 256
static __device__ float g_Y[(size_t)MAX_NODES * DIM];

// ---------------------------------------------------------------------------
// Kernel 1: initialize output with bias (broadcast per row)
// ---------------------------------------------------------------------------
__global__ void init_out_kernel(float* __restrict__ out,
                                const float* __restrict__ bias, int n4) {
    int i = blockIdx.x * blockDim.x + threadIdx.x;
    if (i < n4) {
        float4 b = reinterpret_cast<const float4*>(bias)[i & 63];  // col chunk
        reinterpret_cast<float4*>(out)[i] = b;
    }
}

// ---------------------------------------------------------------------------
// Kernel 2: Y = X @ W   (M x 256) @ (256 x 256), fp32 register-blocked SGEMM
// BM=128, BN=128, BK=16, 256 threads, 8x8 micro-tile per thread.
// ---------------------------------------------------------------------------
#define BM 128
#define BN 128
#define BK 16
#define TM 8
#define TN 8

__global__ __launch_bounds__(256, 2)
void gemm_xw_kernel(const float* __restrict__ A,   // X: M x 256
                    const float* __restrict__ B,   // W: 256 x 256
                    int M) {
    const int K = 256, N = 256;
    __shared__ float As[BK][BM];       // transposed A tile
    __shared__ float Bs[BK][BN];

    const int tid = threadIdx.x;
    const int ty = tid >> 4;           // 0..15
    const int tx = tid & 15;           // 0..15
    const int rowBase = blockIdx.x * BM;
    const int colBase = blockIdx.y * BN;

    float acc[TM][TN] = {};

    for (int k0 = 0; k0 < K; k0 += BK) {
        // --- load A tile (128 x 16) : 512 float4, 2 per thread ---
        #pragma unroll
        for (int i = 0; i < 2; i++) {
            int f  = tid * 2 + i;           // 0..511
            int ar = f >> 2;                // tile row 0..127
            int ac = (f & 3) * 4;           // tile col 0,4,8,12
            int grow = rowBase + ar;
            float4 v = make_float4(0.f, 0.f, 0.f, 0.f);
            if (grow < M)
                v = *reinterpret_cast<const float4*>(A + (size_t)grow * K + k0 + ac);
            As[ac + 0][ar] = v.x;
            As[ac + 1][ar] = v.y;
            As[ac + 2][ar] = v.z;
            As[ac + 3][ar] = v.w;
        }
        // --- load B tile (16 x 128) : 512 float4, 2 per thread ---
        #pragma unroll
        for (int i = 0; i < 2; i++) {
            int f  = tid * 2 + i;
            int br = f >> 5;                // 0..15
            int bc = (f & 31) * 4;          // 0..124
            float4 v = *reinterpret_cast<const float4*>(
                B + (size_t)(k0 + br) * N + colBase + bc);
            *reinterpret_cast<float4*>(&Bs[br][bc]) = v;
        }
        __syncthreads();

        #pragma unroll
        for (int k = 0; k < BK; k++) {
            float ra[TM], rb[TN];
            *reinterpret_cast<float4*>(&ra[0]) =
                *reinterpret_cast<const float4*>(&As[k][ty * TM + 0]);
            *reinterpret_cast<float4*>(&ra[4]) =
                *reinterpret_cast<const float4*>(&As[k][ty * TM + 4]);
            *reinterpret_cast<float4*>(&rb[0]) =
                *reinterpret_cast<const float4*>(&Bs[k][tx * TN + 0]);
            *reinterpret_cast<float4*>(&rb[4]) =
                *reinterpret_cast<const float4*>(&Bs[k][tx * TN + 4]);
            #pragma unroll
            for (int i = 0; i < TM; i++)
                #pragma unroll
                for (int j = 0; j < TN; j++)
                    acc[i][j] += ra[i] * rb[j];
        }
        __syncthreads();
    }

    #pragma unroll
    for (int i = 0; i < TM; i++) {
        int grow = rowBase + ty * TM + i;
        if (grow < M) {
            float* dst = g_Y + (size_t)grow * N + colBase + tx * TN;
            *reinterpret_cast<float4*>(dst + 0) =
                make_float4(acc[i][0], acc[i][1], acc[i][2], acc[i][3]);
            *reinterpret_cast<float4*>(dst + 4) =
                make_float4(acc[i][4], acc[i][5], acc[i][6], acc[i][7]);
        }
    }
}

// ---------------------------------------------------------------------------
// Kernel 3: COO scatter — out[r] += v * Y[c], one warp per edge.
// Uses sm_90+ vector reduction red.global.add.v4.f32 (4x fewer atomic ops).
// ---------------------------------------------------------------------------
__global__ __launch_bounds__(256)
void scatter_kernel(const int* __restrict__ erow,
                    const int* __restrict__ ecol,
                    const float* __restrict__ eval,
                    float* __restrict__ out, int E) {
    int gwarp = (blockIdx.x * blockDim.x + threadIdx.x) >> 5;
    int lane  = threadIdx.x & 31;
    if (gwarp >= E) return;

    int r = erow[gwarp];
    int c = ecol[gwarp];
    float v = eval[gwarp];

    const float4* y = reinterpret_cast<const float4*>(g_Y + (size_t)c * DIM);
    float4*       o = reinterpret_cast<float4*>(out + (size_t)r * DIM);

    #pragma unroll
    for (int j = 0; j < 2; j++) {
        float4 t = __ldg(&y[lane + 32 * j]);
        t.x *= v; t.y *= v; t.z *= v; t.w *= v;
        asm volatile(
            "red.global.add.v4.f32 [%0], {%1, %2, %3, %4};"
            :: "l"(o + lane + 32 * j), "f"(t.x), "f"(t.y), "f"(t.z), "f"(t.w)
            : "memory");
    }
}

// ---------------------------------------------------------------------------
// Launch: out = bias; Y = X@W; out += A@Y   (A(XW) == (AX)W by associativity)
// ---------------------------------------------------------------------------
extern "C" void kernel_launch(void* const* d_in, const int* in_sizes, int n_in,
                              void* d_out, int out_size) {
    const float* X    = (const float*)d_in[0];
    const int*   erow = (const int*)  d_in[1];
    const int*   ecol = (const int*)  d_in[2];
    const float* eval = (const float*)d_in[3];
    const float* W    = (const float*)d_in[4];
    const float* bias = (const float*)d_in[5];
    float* out = (float*)d_out;

    int M = in_sizes[0] / DIM;        // 100000
    int E = in_sizes[1];              // 1600000

    // 1) out[i, :] = bias
    int n4 = M * (DIM / 4);
    init_out_kernel<<<(n4 + 255) / 256, 256>>>(out, bias, n4);

    // 2) Y = X @ W
    dim3 ggrid((M + BM - 1) / BM, DIM / BN);
    gemm_xw_kernel<<<ggrid, 256>>>(X, W, M);

    // 3) out[r] += v * Y[c]   (one warp per edge)
    int warps_per_block = 256 / 32;
    int sblocks = (E + warps_per_block - 1) / warps_per_block;
    scatter_kernel<<<sblocks, 256>>>(erow, ecol, eval, out, E);
}

// round 2
// speedup vs baseline: 1.4670x; 1.4670x over previous
#include <cuda_runtime.h>
#include <cuda_bf16.h>
#include <cstdint>

#define MAX_NODES 100032
#define MAX_EDGES 1600000
#define DIM 256
#define SCAN_B 1024
#define MAX_SCAN_BLOCKS 128

// Scratch (static device globals — no allocation allowed)
static __device__ float g_Y[(size_t)MAX_NODES * DIM];   // Y = X @ W
static __device__ int   g_cnt[MAX_NODES];               // per-row degree
static __device__ int   g_off[MAX_NODES + 1];           // CSR offsets (exclusive scan)
static __device__ int   g_cur[MAX_NODES];               // running cursors for assign
static __device__ int   g_part[MAX_SCAN_BLOCKS];        // scan partials
static __device__ int2  g_cv[MAX_EDGES];                // (col, bitcast(val)) per slot

// ---------------------------------------------------------------------------
// GEMM: Y = X @ W   (M x 256) @ (256 x 256), fp32 register-blocked
// ---------------------------------------------------------------------------
#define BM 128
#define BN 128
#define BK 16
#define TM 8
#define TN 8

__global__ __launch_bounds__(256, 2)
void gemm_xw_kernel(const float* __restrict__ A,
                    const float* __restrict__ B,
                    int M) {
    const int K = 256, N = 256;
    __shared__ float As[BK][BM];
    __shared__ float Bs[BK][BN];

    const int tid = threadIdx.x;
    const int ty = tid >> 4;
    const int tx = tid & 15;
    const int rowBase = blockIdx.x * BM;
    const int colBase = blockIdx.y * BN;

    float acc[TM][TN] = {};

    for (int k0 = 0; k0 < K; k0 += BK) {
        #pragma unroll
        for (int i = 0; i < 2; i++) {
            int f  = tid * 2 + i;
            int ar = f >> 2;
            int ac = (f & 3) * 4;
            int grow = rowBase + ar;
            float4 v = make_float4(0.f, 0.f, 0.f, 0.f);
            if (grow < M)
                v = *reinterpret_cast<const float4*>(A + (size_t)grow * K + k0 + ac);
            As[ac + 0][ar] = v.x;
            As[ac + 1][ar] = v.y;
            As[ac + 2][ar] = v.z;
            As[ac + 3][ar] = v.w;
        }
        #pragma unroll
        for (int i = 0; i < 2; i++) {
            int f  = tid * 2 + i;
            int br = f >> 5;
            int bc = (f & 31) * 4;
            float4 v = *reinterpret_cast<const float4*>(
                B + (size_t)(k0 + br) * N + colBase + bc);
            *reinterpret_cast<float4*>(&Bs[br][bc]) = v;
        }
        __syncthreads();

        #pragma unroll
        for (int k = 0; k < BK; k++) {
            float ra[TM], rb[TN];
            *reinterpret_cast<float4*>(&ra[0]) =
                *reinterpret_cast<const float4*>(&As[k][ty * TM + 0]);
            *reinterpret_cast<float4*>(&ra[4]) =
                *reinterpret_cast<const float4*>(&As[k][ty * TM + 4]);
            *reinterpret_cast<float4*>(&rb[0]) =
                *reinterpret_cast<const float4*>(&Bs[k][tx * TN + 0]);
            *reinterpret_cast<float4*>(&rb[4]) =
                *reinterpret_cast<const float4*>(&Bs[k][tx * TN + 4]);
            #pragma unroll
            for (int i = 0; i < TM; i++)
                #pragma unroll
                for (int j = 0; j < TN; j++)
                    acc[i][j] += ra[i] * rb[j];
        }
        __syncthreads();
    }

    #pragma unroll
    for (int i = 0; i < TM; i++) {
        int grow = rowBase + ty * TM + i;
        if (grow < M) {
            float* dst = g_Y + (size_t)grow * N + colBase + tx * TN;
            *reinterpret_cast<float4*>(dst + 0) =
                make_float4(acc[i][0], acc[i][1], acc[i][2], acc[i][3]);
            *reinterpret_cast<float4*>(dst + 4) =
                make_float4(acc[i][4], acc[i][5], acc[i][6], acc[i][7]);
        }
    }
}

// ---------------------------------------------------------------------------
// CSR build: zero -> histogram -> scan (3 stages) -> assign
// ---------------------------------------------------------------------------
__global__ void zero_cnt_kernel(int M) {
    int i = blockIdx.x * blockDim.x + threadIdx.x;
    if (i < M) g_cnt[i] = 0;
}

__global__ void hist_kernel(const int* __restrict__ erow, int E) {
    int i = blockIdx.x * blockDim.x + threadIdx.x;
    if (i < E) atomicAdd(&g_cnt[erow[i]], 1);
}

__global__ __launch_bounds__(SCAN_B)
void scan1_kernel(int M) {
    __shared__ int sh[SCAN_B];
    int tid = threadIdx.x;
    int i = blockIdx.x * SCAN_B + tid;
    int v = (i < M) ? g_cnt[i] : 0;
    sh[tid] = v;
    __syncthreads();
    #pragma unroll
    for (int d = 1; d < SCAN_B; d <<= 1) {
        int t = (tid >= d) ? sh[tid - d] : 0;
        __syncthreads();
        sh[tid] += t;
        __syncthreads();
    }
    if (i < M) g_off[i] = sh[tid] - v;          // exclusive within block
    if (tid == SCAN_B - 1) g_part[blockIdx.x] = sh[tid];
}

__global__ void scan2_kernel(int nb) {
    // tiny: sequential exclusive scan of block partials
    if (threadIdx.x == 0 && blockIdx.x == 0) {
        int run = 0;
        for (int b = 0; b < nb; b++) {
            int v = g_part[b];
            g_part[b] = run;
            run += v;
        }
    }
}

__global__ void scan3_kernel(int M, int E) {
    int i = blockIdx.x * blockDim.x + threadIdx.x;
    if (i < M) {
        int o = g_off[i] + g_part[i >> 10];
        g_off[i] = o;
        g_cur[i] = o;
    }
    if (i == 0) g_off[M] = E;
}

__global__ void assign_kernel(const int* __restrict__ erow,
                              const int* __restrict__ ecol,
                              const float* __restrict__ eval, int E) {
    int i = blockIdx.x * blockDim.x + threadIdx.x;
    if (i < E) {
        int r = erow[i];
        int p = atomicAdd(&g_cur[r], 1);
        g_cv[p] = make_int2(ecol[i], __float_as_int(eval[i]));
    }
}

// ---------------------------------------------------------------------------
// SpMM over CSR: one warp per row; accumulate D=256 in registers (8/lane),
// bias fused into accumulator init; single coalesced write to out.
// ---------------------------------------------------------------------------
__global__ __launch_bounds__(256)
void spmm_csr_kernel(const float* __restrict__ bias,
                     float* __restrict__ out, int M) {
    int warp = (blockIdx.x * blockDim.x + threadIdx.x) >> 5;
    int lane = threadIdx.x & 31;
    if (warp >= M) return;

    int start = g_off[warp];
    int end   = g_off[warp + 1];

    float4 a0 = reinterpret_cast<const float4*>(bias)[lane * 2 + 0];
    float4 a1 = reinterpret_cast<const float4*>(bias)[lane * 2 + 1];

    for (int base = start; base < end; base += 32) {
        int idx = base + lane;
        int2 cvl = make_int2(0, 0);
        if (idx < end) cvl = g_cv[idx];
        int n = min(32, end - base);

        int j = 0;
        for (; j + 2 <= n; j += 2) {
            int   c0 = __shfl_sync(0xffffffffu, cvl.x, j);
            float v0 = __int_as_float(__shfl_sync(0xffffffffu, cvl.y, j));
            int   c1 = __shfl_sync(0xffffffffu, cvl.x, j + 1);
            float v1 = __int_as_float(__shfl_sync(0xffffffffu, cvl.y, j + 1));
            const float4* y0p = reinterpret_cast<const float4*>(
                g_Y + (size_t)c0 * DIM) + lane * 2;
            const float4* y1p = reinterpret_cast<const float4*>(
                g_Y + (size_t)c1 * DIM) + lane * 2;
            float4 y00 = __ldg(y0p + 0), y01 = __ldg(y0p + 1);
            float4 y10 = __ldg(y1p + 0), y11 = __ldg(y1p + 1);
            a0.x += v0 * y00.x; a0.y += v0 * y00.y; a0.z += v0 * y00.z; a0.w += v0 * y00.w;
            a1.x += v0 * y01.x; a1.y += v0 * y01.y; a1.z += v0 * y01.z; a1.w += v0 * y01.w;
            a0.x += v1 * y10.x; a0.y += v1 * y10.y; a0.z += v1 * y10.z; a0.w += v1 * y10.w;
            a1.x += v1 * y11.x; a1.y += v1 * y11.y; a1.z += v1 * y11.z; a1.w += v1 * y11.w;
        }
        if (j < n) {
            int   c0 = __shfl_sync(0xffffffffu, cvl.x, j);
            float v0 = __int_as_float(__shfl_sync(0xffffffffu, cvl.y, j));
            const float4* y0p = reinterpret_cast<const float4*>(
                g_Y + (size_t)c0 * DIM) + lane * 2;
            float4 y00 = __ldg(y0p + 0), y01 = __ldg(y0p + 1);
            a0.x += v0 * y00.x; a0.y += v0 * y00.y; a0.z += v0 * y00.z; a0.w += v0 * y00.w;
            a1.x += v0 * y01.x; a1.y += v0 * y01.y; a1.z += v0 * y01.z; a1.w += v0 * y01.w;
        }
    }

    float4* o = reinterpret_cast<float4*>(out + (size_t)warp * DIM) + lane * 2;
    o[0] = a0;
    o[1] = a1;
}

// ---------------------------------------------------------------------------
extern "C" void kernel_launch(void* const* d_in, const int* in_sizes, int n_in,
                              void* d_out, int out_size) {
    const float* X    = (const float*)d_in[0];
    const int*   erow = (const int*)  d_in[1];
    const int*   ecol = (const int*)  d_in[2];
    const float* eval = (const float*)d_in[3];
    const float* W    = (const float*)d_in[4];
    const float* bias = (const float*)d_in[5];
    float* out = (float*)d_out;

    int M = in_sizes[0] / DIM;   // 100000
    int E = in_sizes[1];         // 1600000
    int nScanBlocks = (M + SCAN_B - 1) / SCAN_B;

    // CSR build
    zero_cnt_kernel<<<(M + 255) / 256, 256>>>(M);
    hist_kernel<<<(E + 255) / 256, 256>>>(erow, E);
    scan1_kernel<<<nScanBlocks, SCAN_B>>>(M);
    scan2_kernel<<<1, 32>>>(nScanBlocks);
    scan3_kernel<<<(M + 255) / 256, 256>>>(M, E);
    assign_kernel<<<(E + 255) / 256, 256>>>(erow, ecol, eval, E);

    // Y = X @ W (independent of CSR build; must precede spmm)
    dim3 ggrid((M + BM - 1) / BM, DIM / BN);
    gemm_xw_kernel<<<ggrid, 256>>>(X, W, M);

    // out[r] = bias + sum_e v * Y[c]
    int rows_per_block = 256 / 32;
    spmm_csr_kernel<<<(M + rows_per_block - 1) / rows_per_block, 256>>>(bias, out, M);
}

// round 3
// speedup vs baseline: 1.5475x; 1.0549x over previous
#include <cuda_runtime.h>
#include <cuda_bf16.h>
#include <cstdint>

#define MAX_NODES 100032
#define MAX_EDGES 1600000
#define DIM 256
#define SCAN_B 1024
#define MAX_SCAN_BLOCKS 128

// Scratch (static device globals — no allocation allowed)
static __device__ float g_Y[(size_t)MAX_NODES * DIM];   // Y = X @ W
static __device__ int   g_cnt[MAX_NODES];               // per-row degree
static __device__ int   g_off[MAX_NODES + 1];           // CSR offsets
static __device__ int   g_cur[MAX_NODES];               // running cursors
static __device__ int   g_part[MAX_SCAN_BLOCKS];        // scan partials
static __device__ int2  g_cv[MAX_EDGES];                // (col, bitcast(val))

// ---------------------------------------------------------------------------
// f32x2 packed FMA helpers (FFMA2 — only reachable via PTX on sm_103a)
// ---------------------------------------------------------------------------
__device__ __forceinline__ void ffma2(unsigned long long& acc,
                                      unsigned long long a2,
                                      unsigned long long b2) {
    asm("fma.rn.f32x2 %0, %1, %2, %0;" : "+l"(acc) : "l"(a2), "l"(b2));
}
__device__ __forceinline__ unsigned long long dup2(float a) {
    unsigned long long r;
    asm("mov.b64 %0, {%1, %1};" : "=l"(r) : "f"(a));
    return r;
}

// ---------------------------------------------------------------------------
// GEMM: Y = X @ W   (M x 256) @ (256 x 256), fp32 with packed FFMA2
// BM=128, BN=128, BK=16, 256 threads, 8x8 micro-tile (cols packed in pairs)
// ---------------------------------------------------------------------------
#define BM 128
#define BN 128
#define BK 16
#define TM 8
#define TN 8

__global__ __launch_bounds__(256, 2)
void gemm_xw_kernel(const float* __restrict__ A,
                    const float* __restrict__ B,
                    int M) {
    const int K = 256, N = 256;
    __shared__ float As[BK][BM];
    __shared__ float Bs[BK][BN];

    const int tid = threadIdx.x;
    const int ty = tid >> 4;
    const int tx = tid & 15;
    const int rowBase = blockIdx.x * BM;
    const int colBase = blockIdx.y * BN;

    // acc[i][p] holds columns (2p, 2p+1) for micro-row i, packed f32x2
    unsigned long long acc[TM][TN / 2] = {};

    for (int k0 = 0; k0 < K; k0 += BK) {
        #pragma unroll
        for (int i = 0; i < 2; i++) {
            int f  = tid * 2 + i;
            int ar = f >> 2;
            int ac = (f & 3) * 4;
            int grow = rowBase + ar;
            float4 v = make_float4(0.f, 0.f, 0.f, 0.f);
            if (grow < M)
                v = *reinterpret_cast<const float4*>(A + (size_t)grow * K + k0 + ac);
            As[ac + 0][ar] = v.x;
            As[ac + 1][ar] = v.y;
            As[ac + 2][ar] = v.z;
            As[ac + 3][ar] = v.w;
        }
        #pragma unroll
        for (int i = 0; i < 2; i++) {
            int f  = tid * 2 + i;
            int br = f >> 5;
            int bc = (f & 31) * 4;
            float4 v = *reinterpret_cast<const float4*>(
                B + (size_t)(k0 + br) * N + colBase + bc);
            *reinterpret_cast<float4*>(&Bs[br][bc]) = v;
        }
        __syncthreads();

        #pragma unroll
        for (int k = 0; k < BK; k++) {
            float ra[TM];
            *reinterpret_cast<float4*>(&ra[0]) =
                *reinterpret_cast<const float4*>(&As[k][ty * TM + 0]);
            *reinterpret_cast<float4*>(&ra[4]) =
                *reinterpret_cast<const float4*>(&As[k][ty * TM + 4]);
            // b pairs: two consecutive f32 in LE memory == f32x2 pack
            ulonglong2 rb01 = *reinterpret_cast<const ulonglong2*>(&Bs[k][tx * TN + 0]);
            ulonglong2 rb23 = *reinterpret_cast<const ulonglong2*>(&Bs[k][tx * TN + 4]);
            unsigned long long rb[4] = {rb01.x, rb01.y, rb23.x, rb23.y};
            #pragma unroll
            for (int i = 0; i < TM; i++) {
                unsigned long long ad = dup2(ra[i]);
                #pragma unroll
                for (int p = 0; p < TN / 2; p++)
                    ffma2(acc[i][p], ad, rb[p]);
            }
        }
        __syncthreads();
    }

    #pragma unroll
    for (int i = 0; i < TM; i++) {
        int grow = rowBase + ty * TM + i;
        if (grow < M) {
            float* dst = g_Y + (size_t)grow * N + colBase + tx * TN;
            *reinterpret_cast<ulonglong2*>(dst + 0) = make_ulonglong2(acc[i][0], acc[i][1]);
            *reinterpret_cast<ulonglong2*>(dst + 4) = make_ulonglong2(acc[i][2], acc[i][3]);
        }
    }
}

// ---------------------------------------------------------------------------
// CSR build: zero -> histogram -> scan (3 stages) -> assign
// ---------------------------------------------------------------------------
__global__ void zero_cnt_kernel(int M) {
    int i = blockIdx.x * blockDim.x + threadIdx.x;
    if (i < M) g_cnt[i] = 0;
}

__global__ void hist_kernel(const int* __restrict__ erow, int E) {
    int i = blockIdx.x * blockDim.x + threadIdx.x;
    if (i < E) atomicAdd(&g_cnt[erow[i]], 1);
}

__global__ __launch_bounds__(SCAN_B)
void scan1_kernel(int M) {
    __shared__ int sh[SCAN_B];
    int tid = threadIdx.x;
    int i = blockIdx.x * SCAN_B + tid;
    int v = (i < M) ? g_cnt[i] : 0;
    sh[tid] = v;
    __syncthreads();
    #pragma unroll
    for (int d = 1; d < SCAN_B; d <<= 1) {
        int t = (tid >= d) ? sh[tid - d] : 0;
        __syncthreads();
        sh[tid] += t;
        __syncthreads();
    }
    if (i < M) g_off[i] = sh[tid] - v;
    if (tid == SCAN_B - 1) g_part[blockIdx.x] = sh[tid];
}

__global__ __launch_bounds__(MAX_SCAN_BLOCKS)
void scan2_kernel(int nb) {
    // parallel exclusive scan of <=128 block partials (single block)
    __shared__ int sh[MAX_SCAN_BLOCKS];
    int tid = threadIdx.x;
    int v = (tid < nb) ? g_part[tid] : 0;
    sh[tid] = v;
    __syncthreads();
    #pragma unroll
    for (int d = 1; d < MAX_SCAN_BLOCKS; d <<= 1) {
        int t = (tid >= d) ? sh[tid - d] : 0;
        __syncthreads();
        sh[tid] += t;
        __syncthreads();
    }
    if (tid < nb) g_part[tid] = sh[tid] - v;
}

__global__ void scan3_kernel(int M, int E) {
    int i = blockIdx.x * blockDim.x + threadIdx.x;
    if (i < M) {
        int o = g_off[i] + g_part[i >> 10];
        g_off[i] = o;
        g_cur[i] = o;
    }
    if (i == 0) g_off[M] = E;
}

__global__ void assign_kernel(const int* __restrict__ erow,
                              const int* __restrict__ ecol,
                              const float* __restrict__ eval, int E) {
    int i = blockIdx.x * blockDim.x + threadIdx.x;
    if (i < E) {
        int r = erow[i];
        int p = atomicAdd(&g_cur[r], 1);
        g_cv[p] = make_int2(ecol[i], __float_as_int(eval[i]));
    }
}

// ---------------------------------------------------------------------------
// SpMM over CSR: one warp per row; register accumulation, bias fused.
// ---------------------------------------------------------------------------
__global__ __launch_bounds__(256)
void spmm_csr_kernel(const float* __restrict__ bias,
                     float* __restrict__ out, int M) {
    int warp = (blockIdx.x * blockDim.x + threadIdx.x) >> 5;
    int lane = threadIdx.x & 31;
    if (warp >= M) return;

    int start = g_off[warp];
    int end   = g_off[warp + 1];

    float4 a0 = reinterpret_cast<const float4*>(bias)[lane * 2 + 0];
    float4 a1 = reinterpret_cast<const float4*>(bias)[lane * 2 + 1];

    for (int base = start; base < end; base += 32) {
        int idx = base + lane;
        int2 cvl = make_int2(0, 0);
        if (idx < end) cvl = g_cv[idx];
        int n = min(32, end - base);

        int j = 0;
        for (; j + 2 <= n; j += 2) {
            int   c0 = __shfl_sync(0xffffffffu, cvl.x, j);
            float v0 = __int_as_float(__shfl_sync(0xffffffffu, cvl.y, j));
            int   c1 = __shfl_sync(0xffffffffu, cvl.x, j + 1);
            float v1 = __int_as_float(__shfl_sync(0xffffffffu, cvl.y, j + 1));
            const float4* y0p = reinterpret_cast<const float4*>(
                g_Y + (size_t)c0 * DIM) + lane * 2;
            const float4* y1p = reinterpret_cast<const float4*>(
                g_Y + (size_t)c1 * DIM) + lane * 2;
            float4 y00 = __ldg(y0p + 0), y01 = __ldg(y0p + 1);
            float4 y10 = __ldg(y1p + 0), y11 = __ldg(y1p + 1);
            a0.x += v0 * y00.x; a0.y += v0 * y00.y; a0.z += v0 * y00.z; a0.w += v0 * y00.w;
            a1.x += v0 * y01.x; a1.y += v0 * y01.y; a1.z += v0 * y01.z; a1.w += v0 * y01.w;
            a0.x += v1 * y10.x; a0.y += v1 * y10.y; a0.z += v1 * y10.z; a0.w += v1 * y10.w;
            a1.x += v1 * y11.x; a1.y += v1 * y11.y; a1.z += v1 * y11.z; a1.w += v1 * y11.w;
        }
        if (j < n) {
            int   c0 = __shfl_sync(0xffffffffu, cvl.x, j);
            float v0 = __int_as_float(__shfl_sync(0xffffffffu, cvl.y, j));
            const float4* y0p = reinterpret_cast<const float4*>(
                g_Y + (size_t)c0 * DIM) + lane * 2;
            float4 y00 = __ldg(y0p + 0), y01 = __ldg(y0p + 1);
            a0.x += v0 * y00.x; a0.y += v0 * y00.y; a0.z += v0 * y00.z; a0.w += v0 * y00.w;
            a1.x += v0 * y01.x; a1.y += v0 * y01.y; a1.z += v0 * y01.z; a1.w += v0 * y01.w;
        }
    }

    float4* o = reinterpret_cast<float4*>(out + (size_t)warp * DIM) + lane * 2;
    o[0] = a0;
    o[1] = a1;
}

// ---------------------------------------------------------------------------
extern "C" void kernel_launch(void* const* d_in, const int* in_sizes, int n_in,
                              void* d_out, int out_size) {
    const float* X    = (const float*)d_in[0];
    const int*   erow = (const int*)  d_in[1];
    const int*   ecol = (const int*)  d_in[2];
    const float* eval = (const float*)d_in[3];
    const float* W    = (const float*)d_in[4];
    const float* bias = (const float*)d_in[5];
    float* out = (float*)d_out;

    int M = in_sizes[0] / DIM;   // 100000
    int E = in_sizes[1];         // 1600000
    int nScanBlocks = (M + SCAN_B - 1) / SCAN_B;

    // CSR build
    zero_cnt_kernel<<<(M + 255) / 256, 256>>>(M);
    hist_kernel<<<(E + 255) / 256, 256>>>(erow, E);
    scan1_kernel<<<nScanBlocks, SCAN_B>>>(M);
    scan2_kernel<<<1, MAX_SCAN_BLOCKS>>>(nScanBlocks);
    scan3_kernel<<<(M + 255) / 256, 256>>>(M, E);
    assign_kernel<<<(E + 255) / 256, 256>>>(erow, ecol, eval, E);

    // Y = X @ W
    dim3 ggrid((M + BM - 1) / BM, DIM / BN);
    gemm_xw_kernel<<<ggrid, 256>>>(X, W, M);

    // out[r] = bias + sum_e v * Y[c]
    int rows_per_block = 256 / 32;
    spmm_csr_kernel<<<(M + rows_per_block - 1) / rows_per_block, 256>>>(bias, out, M);
}

// round 5
// speedup vs baseline: 2.2196x; 1.4343x over previous
#include <cuda_runtime.h>
#include <cuda_bf16.h>
#include <cstdint>

#define MAX_NODES 100032
#define MAX_EDGES 1600000
#define DIM 256
#define SCAN_B 1024
#define MAX_SCAN_BLOCKS 128

// Scratch (static device globals — no allocation allowed)
static __device__ float g_Y[(size_t)MAX_NODES * DIM];   // Y = X @ W
static __device__ int   g_cnt[MAX_NODES];
static __device__ int   g_off[MAX_NODES + 1];
static __device__ int   g_cur[MAX_NODES];
static __device__ int   g_part[MAX_SCAN_BLOCKS];
static __device__ int2  g_cv[MAX_EDGES];
// Pre-baked mma B fragments of W (bf16 hi/lo split), layout
// [h(2)][k16(16)][hl(2)][n8(16)][lane(32)] of uint2 {b0,b1} = 512 KB
static __device__ uint2 g_Wfrag[2 * 16 * 2 * 16 * 32];

// ---------------------------------------------------------------------------
// helpers
// ---------------------------------------------------------------------------
__device__ __forceinline__ uint32_t smem_u32(const void* p) {
    uint32_t a;
    asm("{ .reg .u64 t; cvta.to.shared.u64 t, %1; cvt.u32.u64 %0, t; }"
        : "=r"(a) : "l"(p));
    return a;
}
__device__ __forceinline__ void ldmatrix_x4(uint32_t* r, uint32_t addr) {
    asm volatile("ldmatrix.sync.aligned.m8n8.x4.shared.b16 {%0,%1,%2,%3}, [%4];"
                 : "=r"(r[0]), "=r"(r[1]), "=r"(r[2]), "=r"(r[3]) : "r"(addr));
}
__device__ __forceinline__ void mma_bf16(float* d, const uint32_t* a, uint2 b) {
    asm volatile(
        "mma.sync.aligned.m16n8k16.row.col.f32.bf16.bf16.f32 "
        "{%0,%1,%2,%3}, {%4,%5,%6,%7}, {%8,%9}, {%0,%1,%2,%3};"
        : "+f"(d[0]), "+f"(d[1]), "+f"(d[2]), "+f"(d[3])
        : "r"(a[0]), "r"(a[1]), "r"(a[2]), "r"(a[3]), "r"(b.x), "r"(b.y));
}
__device__ __forceinline__ uint32_t pack_bf16(float a, float b) {
    __nv_bfloat16 ha = __float2bfloat16(a);
    __nv_bfloat16 hb = __float2bfloat16(b);
    return ((uint32_t)__bfloat16_as_ushort(hb) << 16) |
            (uint32_t)__bfloat16_as_ushort(ha);
}

// ---------------------------------------------------------------------------
// W prep: bf16 split + per-lane mma B-fragment bake.
// b-frag mapping (m16n8k16 row.col): lane holds b0={B[k][n],B[k+1][n]} with
// k=(lane%4)*2, n=lane/4; b1 same with k+8. W input is [K=256][N=256].
// ---------------------------------------------------------------------------
__global__ void wprep_kernel(const float* __restrict__ W) {
    int i = blockIdx.x * blockDim.x + threadIdx.x;
    if (i >= 32768) return;
    int lane = i & 31;
    int n8   = (i >> 5) & 15;
    int hl   = (i >> 9) & 1;
    int k16  = (i >> 10) & 15;
    int h    = (i >> 14) & 1;
    int n  = h * 128 + n8 * 8 + (lane >> 2);
    int kb = k16 * 16 + (lane & 3) * 2;
    uint32_t r[2];
    #pragma unroll
    for (int reg = 0; reg < 2; reg++) {
        int k0 = kb + reg * 8;
        float f0 = W[(size_t)k0 * 256 + n];
        float f1 = W[(size_t)(k0 + 1) * 256 + n];
        if (hl == 0) {
            r[reg] = pack_bf16(f0, f1);
        } else {
            float h0 = __bfloat162float(__float2bfloat16(f0));
            float h1 = __bfloat162float(__float2bfloat16(f1));
            r[reg] = pack_bf16(f0 - h0, f1 - h1);
        }
    }
    g_Wfrag[i] = make_uint2(r[0], r[1]);
}

// ---------------------------------------------------------------------------
// HMMA GEMM: g_Y = X @ W via bf16 3-product split (XhWh + XlWh + XhWl).
// CTA: 128 rows x full N=256, 256 threads (8 warps: 4M x 2N, warp 32x64).
// SMEM: A hi/lo bf16 [128][264] each + B frag double buffer 2x32KB = 196KB.
// ---------------------------------------------------------------------------
#define OFF_AL 67584
#define OFF_B0 135168
#define OFF_B1 167936
#define GEMM_SMEM 200704

__global__ __launch_bounds__(256, 1)
void gemm_tc_kernel(const float* __restrict__ X, int M) {
    extern __shared__ char smem[];
    const int tid   = threadIdx.x;
    const int lane  = tid & 31;
    const int wid   = tid >> 5;
    const int warpM = wid & 3;
    const int warpN = wid >> 2;
    const int rowBase = blockIdx.x * 128;
    const uint32_t sb = smem_u32(smem);

    // ---- load + convert X tile to bf16 hi/lo in smem (row stride 528B) ----
    {
        int r  = tid >> 1;
        int ch = (tid & 1) * 128;
        int grow = rowBase + r;
        const float4* xp = reinterpret_cast<const float4*>(
            X + (size_t)grow * 256 + ch);
        char* dH = smem + (size_t)r * 528 + ch * 2;
        char* dL = dH + OFF_AL;
        #pragma unroll 8
        for (int q = 0; q < 32; q++) {
            float4 v = make_float4(0.f, 0.f, 0.f, 0.f);
            if (grow < M) v = xp[q];
            uint32_t hi0 = pack_bf16(v.x, v.y);
            uint32_t hi1 = pack_bf16(v.z, v.w);
            float rx = v.x - __bfloat162float(__float2bfloat16(v.x));
            float ry = v.y - __bfloat162float(__float2bfloat16(v.y));
            float rz = v.z - __bfloat162float(__float2bfloat16(v.z));
            float rw = v.w - __bfloat162float(__float2bfloat16(v.w));
            uint32_t lo0 = pack_bf16(rx, ry);
            uint32_t lo1 = pack_bf16(rz, rw);
            *reinterpret_cast<uint2*>(dH + q * 8) = make_uint2(hi0, hi1);
            *reinterpret_cast<uint2*>(dL + q * 8) = make_uint2(lo0, lo1);
        }
    }
    __syncthreads();

    uint2* Bb0 = reinterpret_cast<uint2*>(smem + OFF_B0);
    uint2* Bb1 = reinterpret_cast<uint2*>(smem + OFF_B1);

    for (int h = 0; h < 2; h++) {
        float acc[2][8][4];
        #pragma unroll
        for (int t = 0; t < 2; t++)
            #pragma unroll
            for (int nt = 0; nt < 8; nt++)
                #pragma unroll
                for (int e = 0; e < 4; e++)
                    acc[t][nt][e] = 0.f;

        const uint2* gw = g_Wfrag + h * 16384;

        // prologue: copy chunk 0 (4 k16 x 2 hl x 16 n8 x 32 lanes = 32KB)
        {
            const uint4* src = reinterpret_cast<const uint4*>(gw);
            uint4* dst = reinterpret_cast<uint4*>(Bb0);
            #pragma unroll
            for (int q = 0; q < 8; q++)
                dst[tid + q * 256] = src[tid + q * 256];
        }
        __syncthreads();

        for (int c = 0; c < 4; c++) {
            if (c < 3) {  // prefetch next chunk into other buffer
                const uint4* src = reinterpret_cast<const uint4*>(
                    gw + (c + 1) * 4096);
                uint4* dst = reinterpret_cast<uint4*>((c & 1) ? Bb0 : Bb1);
                #pragma unroll
                for (int q = 0; q < 8; q++)
                    dst[tid + q * 256] = src[tid + q * 256];
            }
            const uint2* bb = (c & 1) ? Bb1 : Bb0;

            #pragma unroll
            for (int kk = 0; kk < 4; kk++) {
                int k16g = c * 4 + kk;
                uint32_t aH[2][4], aL[2][4];
                #pragma unroll
                for (int t = 0; t < 2; t++) {
                    uint32_t off = (uint32_t)(warpM * 32 + t * 16 + (lane & 15)) * 528
                                 + (uint32_t)k16g * 32 + (lane >> 4) * 16;
                    ldmatrix_x4(aH[t], sb + off);
                    ldmatrix_x4(aL[t], sb + OFF_AL + off);
                }
                #pragma unroll
                for (int nt = 0; nt < 8; nt++) {
                    int n8 = warpN * 8 + nt;
                    uint2 bH = bb[(kk * 2 + 0) * 512 + n8 * 32 + lane];
                    uint2 bL = bb[(kk * 2 + 1) * 512 + n8 * 32 + lane];
                    mma_bf16(acc[0][nt], aH[0], bH);
                    mma_bf16(acc[1][nt], aH[1], bH);
                    mma_bf16(acc[0][nt], aL[0], bH);
                    mma_bf16(acc[1][nt], aL[1], bH);
                    mma_bf16(acc[0][nt], aH[0], bL);
                    mma_bf16(acc[1][nt], aH[1], bL);
                }
            }
            __syncthreads();
        }

        // epilogue: direct coalesced v2 stores
        #pragma unroll
        for (int t = 0; t < 2; t++) {
            #pragma unroll
            for (int nt = 0; nt < 8; nt++) {
                int row0 = rowBase + warpM * 32 + t * 16 + (lane >> 2);
                int col  = h * 128 + warpN * 64 + nt * 8 + (lane & 3) * 2;
                if (row0 < M)
                    *reinterpret_cast<float2*>(g_Y + (size_t)row0 * 256 + col) =
                        make_float2(acc[t][nt][0], acc[t][nt][1]);
                int row1 = row0 + 8;
                if (row1 < M)
                    *reinterpret_cast<float2*>(g_Y + (size_t)row1 * 256 + col) =
                        make_float2(acc[t][nt][2], acc[t][nt][3]);
            }
        }
        __syncthreads();
    }
}

// ---------------------------------------------------------------------------
// CSR build: zero -> histogram -> scan (3 stages) -> assign
// ---------------------------------------------------------------------------
__global__ void zero_cnt_kernel(int M) {
    int i = blockIdx.x * blockDim.x + threadIdx.x;
    if (i < M) g_cnt[i] = 0;
}

__global__ void hist_kernel(const int* __restrict__ erow, int E) {
    int i = blockIdx.x * blockDim.x + threadIdx.x;
    if (i < E) atomicAdd(&g_cnt[erow[i]], 1);
}

__global__ __launch_bounds__(SCAN_B)
void scan1_kernel(int M) {
    __shared__ int sh[SCAN_B];
    int tid = threadIdx.x;
    int i = blockIdx.x * SCAN_B + tid;
    int v = (i < M) ? g_cnt[i] : 0;
    sh[tid] = v;
    __syncthreads();
    #pragma unroll
    for (int d = 1; d < SCAN_B; d <<= 1) {
        int t = (tid >= d) ? sh[tid - d] : 0;
        __syncthreads();
        sh[tid] += t;
        __syncthreads();
    }
    if (i < M) g_off[i] = sh[tid] - v;
    if (tid == SCAN_B - 1) g_part[blockIdx.x] = sh[tid];
}

__global__ __launch_bounds__(MAX_SCAN_BLOCKS)
void scan2_kernel(int nb) {
    __shared__ int sh[MAX_SCAN_BLOCKS];
    int tid = threadIdx.x;
    int v = (tid < nb) ? g_part[tid] : 0;
    sh[tid] = v;
    __syncthreads();
    #pragma unroll
    for (int d = 1; d < MAX_SCAN_BLOCKS; d <<= 1) {
        int t = (tid >= d) ? sh[tid - d] : 0;
        __syncthreads();
        sh[tid] += t;
        __syncthreads();
    }
    if (tid < nb) g_part[tid] = sh[tid] - v;
}

__global__ void scan3_kernel(int M, int E) {
    int i = blockIdx.x * blockDim.x + threadIdx.x;
    if (i < M) {
        int o = g_off[i] + g_part[i >> 10];
        g_off[i] = o;
        g_cur[i] = o;
    }
    if (i == 0) g_off[M] = E;
}

__global__ void assign_kernel(const int* __restrict__ erow,
                              const int* __restrict__ ecol,
                              const float* __restrict__ eval, int E) {
    int i = blockIdx.x * blockDim.x + threadIdx.x;
    if (i < E) {
        int r = erow[i];
        int p = atomicAdd(&g_cur[r], 1);
        g_cv[p] = make_int2(ecol[i], __float_as_int(eval[i]));
    }
}

// ---------------------------------------------------------------------------
// SpMM over CSR: one warp per row; register accumulation, bias fused.
// ---------------------------------------------------------------------------
__global__ __launch_bounds__(256)
void spmm_csr_kernel(const float* __restrict__ bias,
                     float* __restrict__ out, int M) {
    int warp = (blockIdx.x * blockDim.x + threadIdx.x) >> 5;
    int lane = threadIdx.x & 31;
    if (warp >= M) return;

    int start = g_off[warp];
    int end   = g_off[warp + 1];

    float4 a0 = reinterpret_cast<const float4*>(bias)[lane * 2 + 0];
    float4 a1 = reinterpret_cast<const float4*>(bias)[lane * 2 + 1];

    for (int base = start; base < end; base += 32) {
        int idx = base + lane;
        int2 cvl = make_int2(0, 0);
        if (idx < end) cvl = g_cv[idx];
        int n = min(32, end - base);

        int j = 0;
        for (; j + 2 <= n; j += 2) {
            int   c0 = __shfl_sync(0xffffffffu, cvl.x, j);
            float v0 = __int_as_float(__shfl_sync(0xffffffffu, cvl.y, j));
            int   c1 = __shfl_sync(0xffffffffu, cvl.x, j + 1);
            float v1 = __int_as_float(__shfl_sync(0xffffffffu, cvl.y, j + 1));
            const float4* y0p = reinterpret_cast<const float4*>(
                g_Y + (size_t)c0 * DIM) + lane * 2;
            const float4* y1p = reinterpret_cast<const float4*>(
                g_Y + (size_t)c1 * DIM) + lane * 2;
            float4 y00 = __ldg(y0p + 0), y01 = __ldg(y0p + 1);
            float4 y10 = __ldg(y1p + 0), y11 = __ldg(y1p + 1);
            a0.x += v0 * y00.x; a0.y += v0 * y00.y; a0.z += v0 * y00.z; a0.w += v0 * y00.w;
            a1.x += v0 * y01.x; a1.y += v0 * y01.y; a1.z += v0 * y01.z; a1.w += v0 * y01.w;
            a0.x += v1 * y10.x; a0.y += v1 * y10.y; a0.z += v1 * y10.z; a0.w += v1 * y10.w;
            a1.x += v1 * y11.x; a1.y += v1 * y11.y; a1.z += v1 * y11.z; a1.w += v1 * y11.w;
        }
        if (j < n) {
            int   c0 = __shfl_sync(0xffffffffu, cvl.x, j);
            float v0 = __int_as_float(__shfl_sync(0xffffffffu, cvl.y, j));
            const float4* y0p = reinterpret_cast<const float4*>(
                g_Y + (size_t)c0 * DIM) + lane * 2;
            float4 y00 = __ldg(y0p + 0), y01 = __ldg(y0p + 1);
            a0.x += v0 * y00.x; a0.y += v0 * y00.y; a0.z += v0 * y00.z; a0.w += v0 * y00.w;
            a1.x += v0 * y01.x; a1.y += v0 * y01.y; a1.z += v0 * y01.z; a1.w += v0 * y01.w;
        }
    }

    float4* o = reinterpret_cast<float4*>(out + (size_t)warp * DIM) + lane * 2;
    o[0] = a0;
    o[1] = a1;
}

// ---------------------------------------------------------------------------
extern "C" void kernel_launch(void* const* d_in, const int* in_sizes, int n_in,
                              void* d_out, int out_size) {
    const float* X    = (const float*)d_in[0];
    const int*   erow = (const int*)  d_in[1];
    const int*   ecol = (const int*)  d_in[2];
    const float* eval = (const float*)d_in[3];
    const float* W    = (const float*)d_in[4];
    const float* bias = (const float*)d_in[5];
    float* out = (float*)d_out;

    int M = in_sizes[0] / DIM;   // 100000
    int E = in_sizes[1];         // 1600000
    int nScanBlocks = (M + SCAN_B - 1) / SCAN_B;

    cudaFuncSetAttribute(gemm_tc_kernel,
                         cudaFuncAttributeMaxDynamicSharedMemorySize, GEMM_SMEM);

    // CSR build
    zero_cnt_kernel<<<(M + 255) / 256, 256>>>(M);
    hist_kernel<<<(E + 255) / 256, 256>>>(erow, E);
    scan1_kernel<<<nScanBlocks, SCAN_B>>>(M);
    scan2_kernel<<<1, MAX_SCAN_BLOCKS>>>(nScanBlocks);
    scan3_kernel<<<(M + 255) / 256, 256>>>(M, E);
    assign_kernel<<<(E + 255) / 256, 256>>>(erow, ecol, eval, E);

    // W frag prep + tensor-core GEMM: g_Y = X @ W
    wprep_kernel<<<32768 / 256, 256>>>(W);
    int nTiles = (M + 127) / 128;
    gemm_tc_kernel<<<nTiles, 256, GEMM_SMEM>>>(X, M);

    // out[r] = bias + sum_e v * Y[c]
    int rows_per_block = 256 / 32;
    spmm_csr_kernel<<<(M + rows_per_block - 1) / rows_per_block, 256>>>(bias, out, M);
}